// round 4
// baseline (speedup 1.0000x reference)
#include <cuda_runtime.h>
#include <cuda_fp16.h>
#include <cstdint>

#define BATCH 4
#define SEQ   2048
#define DIN   2048
#define DOUT  2048
#define MTOT  (BATCH * SEQ)   // 8192 tokens
#define GROUP 32
#define NGROUP (DIN / GROUP)  // 64

// GEMM tiling
#define BM 128
#define BN 128
#define BK 32                 // halves per K-chunk
#define STAGES 4
#define NKT (DIN / BK)        // 64
#define PITCH 40              // halves per smem row (80B, conflict-free ldmatrix)
#define A_BYTES (BM * PITCH * 2)      // 10240
#define B_BYTES (BN * PITCH * 2)      // 10240
#define STAGE_B (A_BYTES + B_BYTES)   // 20480
#define SMEM_TOTAL (STAGES * STAGE_B) // 81920

// Scratch (allocation-free rule: __device__ globals)
__device__ __half g_A[(size_t)MTOT * DIN];   // exact integer (q - zp) per token
__device__ __half g_W[(size_t)DOUT * DIN];   // dequantized weights
__device__ float  g_sx[MTOT];                // per-token activation scale

// ---------------------------------------------------------------------------
__device__ __forceinline__ void cp_async16(uint32_t saddr, const void* gaddr) {
    asm volatile("cp.async.cg.shared.global [%0], [%1], 16;\n" :: "r"(saddr), "l"(gaddr));
}
__device__ __forceinline__ void cp_commit() { asm volatile("cp.async.commit_group;\n" ::: "memory"); }
template <int N>
__device__ __forceinline__ void cp_wait() { asm volatile("cp.async.wait_group %0;\n" :: "n"(N) : "memory"); }

// ---------------------------------------------------------------------------
// Kernel 1: per-token asymmetric int8 fake-quant of x (float4 vectorized).
// Stores (q - zp) (integer in [-255,255], EXACT in fp16) and scale separately.
// ---------------------------------------------------------------------------
__global__ void quant_x_kernel(const float4* __restrict__ x) {
    const int token = blockIdx.x;
    const float4* xr = x + (size_t)token * (DIN / 4);
    const int tid = threadIdx.x;  // 256 threads

    float4 v0 = xr[tid];
    float4 v1 = xr[tid + 256];
    float vmin = fminf(fminf(fminf(v0.x, v0.y), fminf(v0.z, v0.w)),
                       fminf(fminf(v1.x, v1.y), fminf(v1.z, v1.w)));
    float vmax = fmaxf(fmaxf(fmaxf(v0.x, v0.y), fmaxf(v0.z, v0.w)),
                       fmaxf(fmaxf(v1.x, v1.y), fmaxf(v1.z, v1.w)));
    vmin = fminf(vmin, 0.0f);
    vmax = fmaxf(vmax, 0.0f);
#pragma unroll
    for (int off = 16; off > 0; off >>= 1) {
        vmin = fminf(vmin, __shfl_xor_sync(0xffffffffu, vmin, off));
        vmax = fmaxf(vmax, __shfl_xor_sync(0xffffffffu, vmax, off));
    }
    __shared__ float smin[8], smax[8];
    if ((tid & 31) == 0) { smin[tid >> 5] = vmin; smax[tid >> 5] = vmax; }
    __syncthreads();
    float bmin = smin[0], bmax = smax[0];
#pragma unroll
    for (int i = 1; i < 8; i++) { bmin = fminf(bmin, smin[i]); bmax = fmaxf(bmax, smax[i]); }

    float scale = (bmax - bmin) / 255.0f;
    scale = fmaxf(scale, 1.1920928955078125e-07f);  // jnp.finfo(f32).eps
    float inv = 1.0f / scale;
    float zp = fminf(fmaxf(-128.0f - rintf(bmin * inv), -128.0f), 127.0f);
    if (tid == 0) g_sx[token] = scale;

    __half2* ar = (__half2*)(g_A + (size_t)token * DIN);
#define QV(f) (fminf(fmaxf(rintf((f) * inv) + zp, -128.0f), 127.0f) - zp)
    ar[2 * tid + 0]         = __floats2half2_rn(QV(v0.x), QV(v0.y));
    ar[2 * tid + 1]         = __floats2half2_rn(QV(v0.z), QV(v0.w));
    ar[2 * (tid + 256) + 0] = __floats2half2_rn(QV(v1.x), QV(v1.y));
    ar[2 * (tid + 256) + 1] = __floats2half2_rn(QV(v1.z), QV(v1.w));
#undef QV
}

// ---------------------------------------------------------------------------
// Kernel 2: int4 grouped weight dequant -> fp16
// ---------------------------------------------------------------------------
__global__ void wdq_kernel(const int4* __restrict__ w_int,
                           const float* __restrict__ ws,
                           const float* __restrict__ wz) {
    const int idx = blockIdx.x * 256 + threadIdx.x;  // over DOUT*DIN/4
    int4 w = w_int[idx];
    const int k4 = idx & (DIN / 4 - 1);
    const int o  = idx / (DIN / 4);
    const int g  = (k4 * 4) / GROUP;
    const float s = ws[o * NGROUP + g];
    const float z = wz[o * NGROUP + g];
    __half2 lo = __floats2half2_rn(((float)w.x - z) * s, ((float)w.y - z) * s);
    __half2 hi = __floats2half2_rn(((float)w.z - z) * s, ((float)w.w - z) * s);
    __half2* dst = (__half2*)g_W + (size_t)idx * 2;
    dst[0] = lo;
    dst[1] = hi;
}

// ---------------------------------------------------------------------------
// Kernel 3: GEMM  out[m,n] = s_x[m] * sum_k A[m,k] * W[n,k]
// 128x128 CTA tile, 8 warps (2x4), warp tile 64x32, 4-stage cp.async
// (wait_group 2 -> 3 chunks in flight), ldmatrix + mma.sync m16n8k16.
// ---------------------------------------------------------------------------
extern __shared__ char dsmem[];

__global__ void __launch_bounds__(256, 2) gemm_kernel(float* __restrict__ out) {
    const int tid  = threadIdx.x;      // 256
    const int lane = tid & 31;
    const int wid  = tid >> 5;
    const int warp_m = wid >> 2;       // 0..1  -> 64 rows
    const int warp_n = wid & 3;        // 0..3  -> 32 cols
    const int bn = blockIdx.x, bm = blockIdx.y;

    const __half* Ag = g_A + (size_t)(bm * BM) * DIN;
    const __half* Wg = g_W + (size_t)(bn * BN) * DIN;

    const uint32_t sb = (uint32_t)__cvta_generic_to_shared(dsmem);

    // cp.async chunk mapping: 512 chunks (A) + 512 (B), 2+2 per thread
    const int arow = tid >> 2;          // 0..63
    const int cc   = (tid & 3) * 8;     // chunk col in halves

    auto load_stage = [&](int s, int kt) {
        const uint32_t aBase = sb + s * STAGE_B;
        const uint32_t bBase = aBase + A_BYTES;
        const int kh = kt * BK;
#pragma unroll
        for (int j = 0; j < 2; j++) {
            const int r = arow + j * 64;
            cp_async16(aBase + (uint32_t)(r * PITCH + cc) * 2,
                       Ag + (size_t)r * DIN + kh + cc);
            cp_async16(bBase + (uint32_t)(r * PITCH + cc) * 2,
                       Wg + (size_t)r * DIN + kh + cc);
        }
        cp_commit();
    };

    float acc[4][4][4];
#pragma unroll
    for (int i = 0; i < 4; i++)
#pragma unroll
        for (int j = 0; j < 4; j++)
#pragma unroll
            for (int r = 0; r < 4; r++) acc[i][j][r] = 0.0f;

    // ldmatrix per-lane offsets (within tile)
    const int a_row = warp_m * 64 + (lane & 15);
    const int a_col = (lane >> 4) * 8;
    const int b_row = warp_n * 32 + (lane & 7) + ((lane >> 4) & 1) * 8;
    const int b_col = ((lane >> 3) & 1) * 8;

    load_stage(0, 0);
    load_stage(1, 1);
    load_stage(2, 2);

#pragma unroll 1
    for (int kt = 0; kt < NKT; kt++) {
        cp_wait<2>();          // oldest group (stage kt) complete
        __syncthreads();
        if (kt + 3 < NKT) load_stage((kt + 3) & (STAGES - 1), kt + 3);
        else cp_commit();      // empty group keeps wait<2> arithmetic exact

        const uint32_t aBase = sb + (kt & (STAGES - 1)) * STAGE_B;
        const uint32_t bBase = aBase + A_BYTES;

#pragma unroll
        for (int ks = 0; ks < 2; ks++) {
            uint32_t af[4][4];
#pragma unroll
            for (int mt = 0; mt < 4; mt++) {
                uint32_t addr = aBase +
                    (uint32_t)(((a_row + mt * 16) * PITCH) + ks * 16 + a_col) * 2;
                asm volatile(
                    "ldmatrix.sync.aligned.m8n8.x4.shared.b16 {%0,%1,%2,%3}, [%4];"
                    : "=r"(af[mt][0]), "=r"(af[mt][1]), "=r"(af[mt][2]), "=r"(af[mt][3])
                    : "r"(addr));
            }
            uint32_t bf[4][2];
#pragma unroll
            for (int p = 0; p < 2; p++) {
                uint32_t addr = bBase +
                    (uint32_t)(((b_row + p * 16) * PITCH) + ks * 16 + b_col) * 2;
                uint32_t r0, r1, r2, r3;
                asm volatile(
                    "ldmatrix.sync.aligned.m8n8.x4.shared.b16 {%0,%1,%2,%3}, [%4];"
                    : "=r"(r0), "=r"(r1), "=r"(r2), "=r"(r3)
                    : "r"(addr));
                bf[2 * p][0] = r0; bf[2 * p][1] = r1;
                bf[2 * p + 1][0] = r2; bf[2 * p + 1][1] = r3;
            }
#pragma unroll
            for (int mt = 0; mt < 4; mt++)
#pragma unroll
                for (int nt = 0; nt < 4; nt++)
                    asm volatile(
                        "mma.sync.aligned.m16n8k16.row.col.f32.f16.f16.f32 "
                        "{%0,%1,%2,%3}, {%4,%5,%6,%7}, {%8,%9}, {%0,%1,%2,%3};"
                        : "+f"(acc[mt][nt][0]), "+f"(acc[mt][nt][1]),
                          "+f"(acc[mt][nt][2]), "+f"(acc[mt][nt][3])
                        : "r"(af[mt][0]), "r"(af[mt][1]), "r"(af[mt][2]), "r"(af[mt][3]),
                          "r"(bf[nt][0]), "r"(bf[nt][1]));
        }
    }

    // Epilogue: scale rows by s_x and store fp32
    const int gm0 = bm * BM + warp_m * 64 + (lane >> 2);
    const int gn0 = bn * BN + warp_n * 32 + (lane & 3) * 2;
#pragma unroll
    for (int mt = 0; mt < 4; mt++) {
        const int r0 = gm0 + mt * 16;
        const float s0 = g_sx[r0];
        const float s1 = g_sx[r0 + 8];
#pragma unroll
        for (int nt = 0; nt < 4; nt++) {
            const int c = gn0 + nt * 8;
            float2 v0 = make_float2(acc[mt][nt][0] * s0, acc[mt][nt][1] * s0);
            float2 v1 = make_float2(acc[mt][nt][2] * s1, acc[mt][nt][3] * s1);
            *(float2*)&out[(size_t)r0 * DOUT + c] = v0;
            *(float2*)&out[(size_t)(r0 + 8) * DOUT + c] = v1;
        }
    }
}

// ---------------------------------------------------------------------------
extern "C" void kernel_launch(void* const* d_in, const int* in_sizes, int n_in,
                              void* d_out, int out_size) {
    (void)in_sizes; (void)n_in; (void)out_size;
    const float* x      = (const float*)d_in[0];
    const int*   w_int  = (const int*)d_in[1];
    const float* w_sc   = (const float*)d_in[2];
    const float* w_zp   = (const float*)d_in[3];
    float* out = (float*)d_out;

    cudaFuncSetAttribute(gemm_kernel, cudaFuncAttributeMaxDynamicSharedMemorySize, SMEM_TOTAL);

    quant_x_kernel<<<MTOT, 256>>>((const float4*)x);
    wdq_kernel<<<(DOUT * DIN / 4) / 256, 256>>>((const int4*)w_int, w_sc, w_zp);
    gemm_kernel<<<dim3(DOUT / BN, MTOT / BM), 256, SMEM_TOTAL>>>(out);
}

// round 5
// speedup vs baseline: 1.5252x; 1.5252x over previous
#include <cuda_runtime.h>
#include <cuda_fp16.h>
#include <cstdint>

#define BATCH 4
#define SEQ   2048
#define DIN   2048
#define DOUT  2048
#define MTOT  (BATCH * SEQ)   // 8192 tokens
#define GROUP 32
#define NGROUP (DIN / GROUP)  // 64

// GEMM tiling (R1-proven config, 3-stage pipeline)
#define BM 128
#define BN 128
#define BK 32                 // halves per K-chunk
#define STAGES 3
#define NKT (DIN / BK)        // 64
#define PITCH 40              // halves per smem row (80B, conflict-free ldmatrix)
#define A_BYTES (BM * PITCH * 2)      // 10240
#define B_BYTES (BN * PITCH * 2)      // 10240
#define STAGE_B (A_BYTES + B_BYTES)   // 20480
#define SMEM_TOTAL (STAGES * STAGE_B) // 61440

// Scratch (allocation-free rule: __device__ globals)
__device__ __half g_A[(size_t)MTOT * DIN];   // exact integer (q - zp) per token
__device__ __half g_W[(size_t)DOUT * DIN];   // dequantized weights
__device__ float  g_sx[MTOT];                // per-token activation scale

// ---------------------------------------------------------------------------
__device__ __forceinline__ void cp_async16(uint32_t saddr, const void* gaddr) {
    asm volatile("cp.async.cg.shared.global [%0], [%1], 16;\n" :: "r"(saddr), "l"(gaddr));
}
__device__ __forceinline__ void cp_commit() { asm volatile("cp.async.commit_group;\n" ::: "memory"); }
template <int N>
__device__ __forceinline__ void cp_wait() { asm volatile("cp.async.wait_group %0;\n" :: "n"(N) : "memory"); }

// ---------------------------------------------------------------------------
// Kernel 1: per-token asymmetric int8 fake-quant of x (float4 vectorized).
// Stores (q - zp) (integer in [-255,255], EXACT in fp16) and scale separately.
// ---------------------------------------------------------------------------
__global__ void quant_x_kernel(const float4* __restrict__ x) {
    const int token = blockIdx.x;
    const float4* xr = x + (size_t)token * (DIN / 4);
    const int tid = threadIdx.x;  // 256 threads

    float4 v0 = xr[tid];
    float4 v1 = xr[tid + 256];
    float vmin = fminf(fminf(fminf(v0.x, v0.y), fminf(v0.z, v0.w)),
                       fminf(fminf(v1.x, v1.y), fminf(v1.z, v1.w)));
    float vmax = fmaxf(fmaxf(fmaxf(v0.x, v0.y), fmaxf(v0.z, v0.w)),
                       fmaxf(fmaxf(v1.x, v1.y), fmaxf(v1.z, v1.w)));
    vmin = fminf(vmin, 0.0f);
    vmax = fmaxf(vmax, 0.0f);
#pragma unroll
    for (int off = 16; off > 0; off >>= 1) {
        vmin = fminf(vmin, __shfl_xor_sync(0xffffffffu, vmin, off));
        vmax = fmaxf(vmax, __shfl_xor_sync(0xffffffffu, vmax, off));
    }
    __shared__ float smin[8], smax[8];
    if ((tid & 31) == 0) { smin[tid >> 5] = vmin; smax[tid >> 5] = vmax; }
    __syncthreads();
    float bmin = smin[0], bmax = smax[0];
#pragma unroll
    for (int i = 1; i < 8; i++) { bmin = fminf(bmin, smin[i]); bmax = fmaxf(bmax, smax[i]); }

    float scale = (bmax - bmin) / 255.0f;
    scale = fmaxf(scale, 1.1920928955078125e-07f);  // jnp.finfo(f32).eps
    float inv = 1.0f / scale;
    float zp = fminf(fmaxf(-128.0f - rintf(bmin * inv), -128.0f), 127.0f);
    if (tid == 0) g_sx[token] = scale;

    __half2* ar = (__half2*)(g_A + (size_t)token * DIN);
#define QV(f) (fminf(fmaxf(rintf((f) * inv) + zp, -128.0f), 127.0f) - zp)
    ar[2 * tid + 0]         = __floats2half2_rn(QV(v0.x), QV(v0.y));
    ar[2 * tid + 1]         = __floats2half2_rn(QV(v0.z), QV(v0.w));
    ar[2 * (tid + 256) + 0] = __floats2half2_rn(QV(v1.x), QV(v1.y));
    ar[2 * (tid + 256) + 1] = __floats2half2_rn(QV(v1.z), QV(v1.w));
#undef QV
}

// ---------------------------------------------------------------------------
// Kernel 2: int4 grouped weight dequant -> fp16
// ---------------------------------------------------------------------------
__global__ void wdq_kernel(const int4* __restrict__ w_int,
                           const float* __restrict__ ws,
                           const float* __restrict__ wz) {
    const int idx = blockIdx.x * 256 + threadIdx.x;  // over DOUT*DIN/4
    int4 w = w_int[idx];
    const int k4 = idx & (DIN / 4 - 1);
    const int o  = idx / (DIN / 4);
    const int g  = (k4 * 4) / GROUP;
    const float s = ws[o * NGROUP + g];
    const float z = wz[o * NGROUP + g];
    __half2 lo = __floats2half2_rn(((float)w.x - z) * s, ((float)w.y - z) * s);
    __half2 hi = __floats2half2_rn(((float)w.z - z) * s, ((float)w.w - z) * s);
    __half2* dst = (__half2*)g_W + (size_t)idx * 2;
    dst[0] = lo;
    dst[1] = hi;
}

// ---------------------------------------------------------------------------
// Kernel 3: GEMM  out[m,n] = s_x[m] * sum_k A[m,k] * W[n,k]
// 128x128 CTA tile, 8 warps (2x4), warp tile 64x32, 3-stage cp.async
// (wait_group 1 -> next chunk always in flight), ldmatrix + mma.sync m16n8k16.
// ---------------------------------------------------------------------------
extern __shared__ char dsmem[];

__global__ void gemm_kernel(float* __restrict__ out) {
    const int tid  = threadIdx.x;      // 256
    const int lane = tid & 31;
    const int wid  = tid >> 5;
    const int warp_m = wid >> 2;       // 0..1  -> 64 rows
    const int warp_n = wid & 3;        // 0..3  -> 32 cols
    const int bn = blockIdx.x, bm = blockIdx.y;

    const __half* Ag = g_A + (size_t)(bm * BM) * DIN;
    const __half* Wg = g_W + (size_t)(bn * BN) * DIN;

    const uint32_t sb = (uint32_t)__cvta_generic_to_shared(dsmem);

    // cp.async chunk mapping: 512 chunks (A) + 512 (B), 2+2 per thread
    const int arow = tid >> 2;          // 0..63
    const int cc   = (tid & 3) * 8;     // chunk col in halves

    auto load_stage = [&](int s, int kt) {
        const uint32_t aBase = sb + s * STAGE_B;
        const uint32_t bBase = aBase + A_BYTES;
        const int kh = kt * BK;
#pragma unroll
        for (int j = 0; j < 2; j++) {
            const int r = arow + j * 64;
            cp_async16(aBase + (uint32_t)(r * PITCH + cc) * 2,
                       Ag + (size_t)r * DIN + kh + cc);
            cp_async16(bBase + (uint32_t)(r * PITCH + cc) * 2,
                       Wg + (size_t)r * DIN + kh + cc);
        }
        cp_commit();
    };

    float acc[4][4][4];
#pragma unroll
    for (int i = 0; i < 4; i++)
#pragma unroll
        for (int j = 0; j < 4; j++)
#pragma unroll
            for (int r = 0; r < 4; r++) acc[i][j][r] = 0.0f;

    // ldmatrix per-lane offsets (within tile)
    const int a_row = warp_m * 64 + (lane & 15);
    const int a_col = (lane >> 4) * 8;
    const int b_row = warp_n * 32 + (lane & 7) + ((lane >> 4) & 1) * 8;
    const int b_col = ((lane >> 3) & 1) * 8;

    load_stage(0, 0);
    load_stage(1, 1);

    int s_cur = 0, s_nxt = 2;   // rotating stage indices (avoid %3 in loop)
#pragma unroll 1
    for (int kt = 0; kt < NKT; kt++) {
        if (kt + 1 < NKT) cp_wait<1>(); else cp_wait<0>();
        __syncthreads();
        if (kt + 2 < NKT) load_stage(s_nxt, kt + 2);

        const uint32_t aBase = sb + s_cur * STAGE_B;
        const uint32_t bBase = aBase + A_BYTES;
        s_nxt = s_cur;
        s_cur = (s_cur == 2) ? 0 : s_cur + 1;

#pragma unroll
        for (int ks = 0; ks < 2; ks++) {
            uint32_t af[4][4];
#pragma unroll
            for (int mt = 0; mt < 4; mt++) {
                uint32_t addr = aBase +
                    (uint32_t)(((a_row + mt * 16) * PITCH) + ks * 16 + a_col) * 2;
                asm volatile(
                    "ldmatrix.sync.aligned.m8n8.x4.shared.b16 {%0,%1,%2,%3}, [%4];"
                    : "=r"(af[mt][0]), "=r"(af[mt][1]), "=r"(af[mt][2]), "=r"(af[mt][3])
                    : "r"(addr));
            }
            uint32_t bf[4][2];
#pragma unroll
            for (int p = 0; p < 2; p++) {
                uint32_t addr = bBase +
                    (uint32_t)(((b_row + p * 16) * PITCH) + ks * 16 + b_col) * 2;
                uint32_t r0, r1, r2, r3;
                asm volatile(
                    "ldmatrix.sync.aligned.m8n8.x4.shared.b16 {%0,%1,%2,%3}, [%4];"
                    : "=r"(r0), "=r"(r1), "=r"(r2), "=r"(r3)
                    : "r"(addr));
                bf[2 * p][0] = r0; bf[2 * p][1] = r1;
                bf[2 * p + 1][0] = r2; bf[2 * p + 1][1] = r3;
            }
#pragma unroll
            for (int mt = 0; mt < 4; mt++)
#pragma unroll
                for (int nt = 0; nt < 4; nt++)
                    asm volatile(
                        "mma.sync.aligned.m16n8k16.row.col.f32.f16.f16.f32 "
                        "{%0,%1,%2,%3}, {%4,%5,%6,%7}, {%8,%9}, {%0,%1,%2,%3};"
                        : "+f"(acc[mt][nt][0]), "+f"(acc[mt][nt][1]),
                          "+f"(acc[mt][nt][2]), "+f"(acc[mt][nt][3])
                        : "r"(af[mt][0]), "r"(af[mt][1]), "r"(af[mt][2]), "r"(af[mt][3]),
                          "r"(bf[nt][0]), "r"(bf[nt][1]));
        }
    }

    // Epilogue: scale rows by s_x and store fp32
    const int gm0 = bm * BM + warp_m * 64 + (lane >> 2);
    const int gn0 = bn * BN + warp_n * 32 + (lane & 3) * 2;
#pragma unroll
    for (int mt = 0; mt < 4; mt++) {
        const int r0 = gm0 + mt * 16;
        const float s0 = g_sx[r0];
        const float s1 = g_sx[r0 + 8];
#pragma unroll
        for (int nt = 0; nt < 4; nt++) {
            const int c = gn0 + nt * 8;
            float2 v0 = make_float2(acc[mt][nt][0] * s0, acc[mt][nt][1] * s0);
            float2 v1 = make_float2(acc[mt][nt][2] * s1, acc[mt][nt][3] * s1);
            *(float2*)&out[(size_t)r0 * DOUT + c] = v0;
            *(float2*)&out[(size_t)(r0 + 8) * DOUT + c] = v1;
        }
    }
}

// ---------------------------------------------------------------------------
extern "C" void kernel_launch(void* const* d_in, const int* in_sizes, int n_in,
                              void* d_out, int out_size) {
    (void)in_sizes; (void)n_in; (void)out_size;
    const float* x      = (const float*)d_in[0];
    const int*   w_int  = (const int*)d_in[1];
    const float* w_sc   = (const float*)d_in[2];
    const float* w_zp   = (const float*)d_in[3];
    float* out = (float*)d_out;

    cudaFuncSetAttribute(gemm_kernel, cudaFuncAttributeMaxDynamicSharedMemorySize, SMEM_TOTAL);

    quant_x_kernel<<<MTOT, 256>>>((const float4*)x);
    wdq_kernel<<<(DOUT * DIN / 4) / 256, 256>>>((const int4*)w_int, w_sc, w_zp);
    gemm_kernel<<<dim3(DOUT / BN, MTOT / BM), 256, SMEM_TOTAL>>>(out);
}